// round 13
// baseline (speedup 1.0000x reference)
#include <cuda_runtime.h>
#include <cstdint>

#define NB 4
#define NS 4096
#define ND 1024
#define NV 32000
#define ND3 3072

#define QK_DSPLIT 64
#define QK_DCH (ND / QK_DSPLIT)      // 16
#define HB_CHUNK 256
#define HB_ROWS (NS / HB_CHUNK)      // 16
#define V_DSPLIT 64
#define V_DCH (ND / V_DSPLIT)        // 16
#define O_DSPLIT 8
#define O_DCH (ND / O_DSPLIT)        // 128

// ---------------- scratch (device globals; no allocation allowed) ----------
__device__ __align__(16) float g_hlast[NB][ND];
__device__ __align__(16) float g_q_part[QK_DSPLIT][NB][ND];
__device__ __align__(16) float g_qlast[NB][ND];
__device__ __align__(16) float g_qk[NB][ND];          // pre-scaled by 1/32
__device__ float g_qbk[NB];                           // pre-scaled by 1/32
__device__ __align__(16) float g_logits[NB][NS];      // reused as attn
__device__ __align__(16) float g_hbar_part[HB_CHUNK][NB][ND];
__device__ __align__(16) float g_v_part[V_DSPLIT][NB][ND];
__device__ __align__(16) float g_hfinal[NB][ND];
__device__ __align__(16) float g_out_part[O_DSPLIT][NB][NV];

__device__ __forceinline__ int get_idx(const void* x, int i, bool is64) {
    if (is64) return (int)((const long long*)x)[i];
    return ((const int*)x)[i];
}

// ---------------- K1a: q_last partials = h_last @ Wq -----------------------
// Grid (4, 64): 256 blocks. 256 threads = 64 col-groups (float4) x 4 d-groups.
__global__ void k1a_qpart(const void* __restrict__ x,
                          const float* __restrict__ embed,
                          const float* __restrict__ qkv_w) {
    __shared__ float  sh[NB][QK_DCH];
    __shared__ float4 sred[4][NB][64];
    const int tid = threadIdx.x;
    // Inline int64 detection: first 64 odd int32 words are zero iff int64.
    int vdet = (tid < 64) ? ((const int*)x)[2 * tid + 1] : 0;
    const bool is64 = (__syncthreads_or(vdet) == 0);
    const int dch = blockIdx.y;
    if (tid < NB * QK_DCH) {
        int b = tid / QK_DCH, d = tid % QK_DCH;
        int row = get_idx(x, b * NS + NS - 1, is64);
        float v = embed[(size_t)row * ND + dch * QK_DCH + d];
        sh[b][d] = v;
        if (blockIdx.x == 0) g_hlast[b][dch * QK_DCH + d] = v;
    }
    __syncthreads();
    const int cg = tid & 63, dg = tid >> 6;
    const int j = blockIdx.x * 256 + cg * 4;
    float4 a0 = {0,0,0,0}, a1 = {0,0,0,0}, a2 = {0,0,0,0}, a3 = {0,0,0,0};
#pragma unroll
    for (int i = 0; i < 4; i++) {
        const int d = dg * 4 + i;
        float4 w = *(const float4*)(qkv_w + (size_t)(dch * QK_DCH + d) * ND3 + j);
        float h0 = sh[0][d], h1 = sh[1][d], h2 = sh[2][d], h3 = sh[3][d];
        a0.x = fmaf(h0, w.x, a0.x); a0.y = fmaf(h0, w.y, a0.y);
        a0.z = fmaf(h0, w.z, a0.z); a0.w = fmaf(h0, w.w, a0.w);
        a1.x = fmaf(h1, w.x, a1.x); a1.y = fmaf(h1, w.y, a1.y);
        a1.z = fmaf(h1, w.z, a1.z); a1.w = fmaf(h1, w.w, a1.w);
        a2.x = fmaf(h2, w.x, a2.x); a2.y = fmaf(h2, w.y, a2.y);
        a2.z = fmaf(h2, w.z, a2.z); a2.w = fmaf(h2, w.w, a2.w);
        a3.x = fmaf(h3, w.x, a3.x); a3.y = fmaf(h3, w.y, a3.y);
        a3.z = fmaf(h3, w.z, a3.z); a3.w = fmaf(h3, w.w, a3.w);
    }
    sred[dg][0][cg] = a0;
    sred[dg][1][cg] = a1;
    sred[dg][2][cg] = a2;
    sred[dg][3][cg] = a3;
    __syncthreads();
    {
        const int b = tid >> 6, l = tid & 63;
        float4 s0 = sred[0][b][l], s1 = sred[1][b][l];
        float4 s2 = sred[2][b][l], s3 = sred[3][b][l];
        float4 r;
        r.x = (s0.x + s1.x) + (s2.x + s3.x);
        r.y = (s0.y + s1.y) + (s2.y + s3.y);
        r.z = (s0.z + s1.z) + (s2.z + s3.z);
        r.w = (s0.w + s1.w) + (s2.w + s3.w);
        *(float4*)&g_q_part[dch][b][blockIdx.x * 256 + l * 4] = r;
    }
}

// ---------------- K1ar: reduce partials + bias -> q_last -------------------
__global__ void k1ar_qreduce(const float* __restrict__ qkv_b) {
    int idx = blockIdx.x * 128 + threadIdx.x;     // 32 blocks
    int b = idx >> 10, j = idx & (ND - 1);
    float s = qkv_b[j];
#pragma unroll
    for (int c = 0; c < QK_DSPLIT; c++) s += g_q_part[c][b][j];
    g_qlast[b][j] = s;
}

// ---------------- K1b: qk[j] = Wk-row(j) . q_last --------------------------
// Weight loads issued BEFORE the smem q-preload barrier so the two latency
// rounds overlap.
__global__ void k1b_qk(const float* __restrict__ qkv_w,
                       const float* __restrict__ qkv_b) {
    __shared__ float4 sq[NB][256];    // qlast, 16 KB
    __shared__ float red[2][4][NB];
    const int tid = threadIdx.x, warp = tid >> 5, lane = tid & 31;
    const float kInv = 0.03125f;                  // 1/sqrt(1024)
    if (blockIdx.x < 512) {
        const int rloc = warp >> 2;               // 0..1
        const int quad = warp & 3;                // 0..3
        const int j = blockIdx.x * 2 + rloc;
        const float4* wrow = (const float4*)(qkv_w + (size_t)j * ND3 + ND);
        const int p0 = quad * 64 + lane;
        const int p1 = quad * 64 + 32 + lane;
        // Issue weight loads first (independent of smem).
        float4 w0 = wrow[p0];
        float4 w1 = wrow[p1];
        // Cooperative q preload: 4 independent 16B loads per thread.
        {
            float4 t0 = ((const float4*)g_qlast[0])[tid];
            float4 t1 = ((const float4*)g_qlast[1])[tid];
            float4 t2 = ((const float4*)g_qlast[2])[tid];
            float4 t3 = ((const float4*)g_qlast[3])[tid];
            sq[0][tid] = t0; sq[1][tid] = t1; sq[2][tid] = t2; sq[3][tid] = t3;
        }
        __syncthreads();
        float a0, a1, a2, a3;
        {
            float4 q0 = sq[0][p0], q1 = sq[1][p0], q2 = sq[2][p0], q3 = sq[3][p0];
            a0 = fmaf(w0.x, q0.x, fmaf(w0.y, q0.y, fmaf(w0.z, q0.z, w0.w * q0.w)));
            a1 = fmaf(w0.x, q1.x, fmaf(w0.y, q1.y, fmaf(w0.z, q1.z, w0.w * q1.w)));
            a2 = fmaf(w0.x, q2.x, fmaf(w0.y, q2.y, fmaf(w0.z, q2.z, w0.w * q2.w)));
            a3 = fmaf(w0.x, q3.x, fmaf(w0.y, q3.y, fmaf(w0.z, q3.z, w0.w * q3.w)));
        }
        {
            float4 q0 = sq[0][p1], q1 = sq[1][p1], q2 = sq[2][p1], q3 = sq[3][p1];
            a0 = fmaf(w1.x, q0.x, fmaf(w1.y, q0.y, fmaf(w1.z, q0.z, fmaf(w1.w, q0.w, a0))));
            a1 = fmaf(w1.x, q1.x, fmaf(w1.y, q1.y, fmaf(w1.z, q1.z, fmaf(w1.w, q1.w, a1))));
            a2 = fmaf(w1.x, q2.x, fmaf(w1.y, q2.y, fmaf(w1.z, q2.z, fmaf(w1.w, q2.w, a2))));
            a3 = fmaf(w1.x, q3.x, fmaf(w1.y, q3.y, fmaf(w1.z, q3.z, fmaf(w1.w, q3.w, a3))));
        }
#pragma unroll
        for (int o = 16; o > 0; o >>= 1) {
            a0 += __shfl_xor_sync(0xffffffffu, a0, o);
            a1 += __shfl_xor_sync(0xffffffffu, a1, o);
            a2 += __shfl_xor_sync(0xffffffffu, a2, o);
            a3 += __shfl_xor_sync(0xffffffffu, a3, o);
        }
        if (lane == 0) {
            red[rloc][quad][0] = a0; red[rloc][quad][1] = a1;
            red[rloc][quad][2] = a2; red[rloc][quad][3] = a3;
        }
        __syncthreads();
        if (tid < 8) {
            int r = tid >> 2, b = tid & 3;
            float s = red[r][0][b] + red[r][1][b] + red[r][2][b] + red[r][3][b];
            g_qk[b][blockIdx.x * 2 + r] = s * kInv;
        }
    } else {
        if (warp < NB) {
            const float4* bk = (const float4*)(qkv_b + ND);
            const float4* q  = (const float4*)g_qlast[warp];
            float a = 0.f;
#pragma unroll
            for (int it = 0; it < 8; it++) {
                int p = lane + 32 * it;
                float4 w = bk[p];
                float4 qq = q[p];
                a = fmaf(w.x, qq.x, fmaf(w.y, qq.y, fmaf(w.z, qq.z, fmaf(w.w, qq.w, a))));
            }
#pragma unroll
            for (int o = 16; o > 0; o >>= 1) a += __shfl_xor_sync(0xffffffffu, a, o);
            if (lane == 0) g_qbk[warp] = a * kInv;
        }
    }
}

// ---------------- K2: logits[b][s] = embed[x[b,s]] . qk[b] + qbk[b] --------
__global__ void k2_logits(const void* __restrict__ x,
                          const float* __restrict__ embed) {
    __shared__ float4 sqk[256];
    const int b = blockIdx.y;
    const int tid = threadIdx.x;
    int vdet = (tid < 64) ? ((const int*)x)[2 * tid + 1] : 0;
    sqk[tid] = ((const float4*)g_qk[b])[tid];
    const bool is64 = (__syncthreads_or(vdet) == 0);   // also the sqk barrier
    const int warp = tid >> 5, lane = tid & 31;
    const int s0 = blockIdx.x * 16 + warp * 2;
    const int rowA = get_idx(x, b * NS + s0, is64);
    const int rowB = get_idx(x, b * NS + s0 + 1, is64);
    const float4* eA = (const float4*)(embed + (size_t)rowA * ND);
    const float4* eB = (const float4*)(embed + (size_t)rowB * ND);
    float a = 0.f, c = 0.f;
#pragma unroll
    for (int it = 0; it < 8; it++) {
        int p = lane + 32 * it;
        float4 q  = sqk[p];
        float4 va = eA[p];
        float4 vb = eB[p];
        a = fmaf(va.x, q.x, fmaf(va.y, q.y, fmaf(va.z, q.z, fmaf(va.w, q.w, a))));
        c = fmaf(vb.x, q.x, fmaf(vb.y, q.y, fmaf(vb.z, q.z, fmaf(vb.w, q.w, c))));
    }
#pragma unroll
    for (int o = 16; o > 0; o >>= 1) {
        a += __shfl_xor_sync(0xffffffffu, a, o);
        c += __shfl_xor_sync(0xffffffffu, c, o);
    }
    if (lane == 0) {
        float qb = g_qbk[b];
        g_logits[b][s0]     = a + qb;
        g_logits[b][s0 + 1] = c + qb;
    }
}

// ---------------- K3: softmax over 4096 keys, in place ---------------------
__global__ void k3_softmax() {
    __shared__ float red[32];
    __shared__ float bcast;
    const int b = blockIdx.x, t = threadIdx.x;
    const int lane = t & 31, warp = t >> 5;
    float l0 = g_logits[b][t];
    float l1 = g_logits[b][t + 1024];
    float l2 = g_logits[b][t + 2048];
    float l3 = g_logits[b][t + 3072];
    float m = fmaxf(fmaxf(l0, l1), fmaxf(l2, l3));
#pragma unroll
    for (int o = 16; o > 0; o >>= 1) m = fmaxf(m, __shfl_xor_sync(0xffffffffu, m, o));
    if (lane == 0) red[warp] = m;
    __syncthreads();
    if (t < 32) {
        float mm = red[t];
#pragma unroll
        for (int o = 16; o > 0; o >>= 1) mm = fmaxf(mm, __shfl_xor_sync(0xffffffffu, mm, o));
        if (t == 0) bcast = mm;
    }
    __syncthreads();
    const float M = bcast;
    float e0 = expf(l0 - M), e1 = expf(l1 - M), e2 = expf(l2 - M), e3 = expf(l3 - M);
    float s = (e0 + e1) + (e2 + e3);
#pragma unroll
    for (int o = 16; o > 0; o >>= 1) s += __shfl_xor_sync(0xffffffffu, s, o);
    __syncthreads();
    if (lane == 0) red[warp] = s;
    __syncthreads();
    if (t < 32) {
        float ss = red[t];
#pragma unroll
        for (int o = 16; o > 0; o >>= 1) ss += __shfl_xor_sync(0xffffffffu, ss, o);
        if (t == 0) bcast = ss;
    }
    __syncthreads();
    const float inv = 1.0f / bcast;
    g_logits[b][t]        = e0 * inv;
    g_logits[b][t + 1024] = e1 * inv;
    g_logits[b][t + 2048] = e2 * inv;
    g_logits[b][t + 3072] = e3 * inv;
}

// ---------------- K4: hbar partials = sum_s attn[b,s] * embed[x[b,s]] ------
__global__ void k4_hbar(const void* __restrict__ x,
                        const float* __restrict__ embed) {
    const int c = blockIdx.x, b = blockIdx.y;
    const int t = threadIdx.x;
    int vdet = (t < 64) ? ((const int*)x)[2 * t + 1] : 0;
    const bool is64 = (__syncthreads_or(vdet) == 0);
    float4 acc = make_float4(0.f, 0.f, 0.f, 0.f);
    const int s0 = c * HB_ROWS;
#pragma unroll 8
    for (int r = 0; r < HB_ROWS; r++) {
        int s = s0 + r;
        float w = g_logits[b][s];
        int row = get_idx(x, b * NS + s, is64);
        float4 e = ((const float4*)(embed + (size_t)row * ND))[t];
        acc.x = fmaf(w, e.x, acc.x);
        acc.y = fmaf(w, e.y, acc.y);
        acc.z = fmaf(w, e.z, acc.z);
        acc.w = fmaf(w, e.w, acc.w);
    }
    ((float4*)g_hbar_part[c][b])[t] = acc;
}

// ---------------- K5a: v partials = hbar @ Wv ------------------------------
__global__ void k5a_vpart(const float* __restrict__ qkv_w) {
    __shared__ float  psum[4][NB][V_DCH];
    __shared__ float  sh[NB][V_DCH];
    __shared__ float4 sred[4][NB][64];
    const int dch = blockIdx.y;
    const int tid = threadIdx.x;
    {   // preamble: sh[b][d] = sum_c hbar_part[c][b][dch*16+d], 256-way
        const int cgrp = tid >> 6;            // 0..3 (64 chunks each)
        const int rem = tid & 63;
        const int b = rem >> 4, d = rem & 15;
        float s = 0.f;
#pragma unroll 8
        for (int k = 0; k < HB_CHUNK / 4; k++)
            s += g_hbar_part[cgrp * (HB_CHUNK / 4) + k][b][dch * V_DCH + d];
        psum[cgrp][b][d] = s;
        __syncthreads();
        if (tid < NB * V_DCH) {
            int bb = tid >> 4, dd = tid & 15;
            sh[bb][dd] = (psum[0][bb][dd] + psum[1][bb][dd])
                       + (psum[2][bb][dd] + psum[3][bb][dd]);
        }
        __syncthreads();
    }
    const int cg = tid & 63, dg = tid >> 6;
    const int j = blockIdx.x * 256 + cg * 4;
    float4 a0 = {0,0,0,0}, a1 = {0,0,0,0}, a2 = {0,0,0,0}, a3 = {0,0,0,0};
#pragma unroll
    for (int i = 0; i < 4; i++) {
        const int d = dg * 4 + i;
        float4 w = *(const float4*)(qkv_w + (size_t)(dch * V_DCH + d) * ND3 + 2048 + j);
        float h0 = sh[0][d], h1 = sh[1][d], h2 = sh[2][d], h3 = sh[3][d];
        a0.x = fmaf(h0, w.x, a0.x); a0.y = fmaf(h0, w.y, a0.y);
        a0.z = fmaf(h0, w.z, a0.z); a0.w = fmaf(h0, w.w, a0.w);
        a1.x = fmaf(h1, w.x, a1.x); a1.y = fmaf(h1, w.y, a1.y);
        a1.z = fmaf(h1, w.z, a1.z); a1.w = fmaf(h1, w.w, a1.w);
        a2.x = fmaf(h2, w.x, a2.x); a2.y = fmaf(h2, w.y, a2.y);
        a2.z = fmaf(h2, w.z, a2.z); a2.w = fmaf(h2, w.w, a2.w);
        a3.x = fmaf(h3, w.x, a3.x); a3.y = fmaf(h3, w.y, a3.y);
        a3.z = fmaf(h3, w.z, a3.z); a3.w = fmaf(h3, w.w, a3.w);
    }
    sred[dg][0][cg] = a0;
    sred[dg][1][cg] = a1;
    sred[dg][2][cg] = a2;
    sred[dg][3][cg] = a3;
    __syncthreads();
    {
        const int b = tid >> 6, l = tid & 63;
        float4 s0 = sred[0][b][l], s1 = sred[1][b][l];
        float4 s2 = sred[2][b][l], s3 = sred[3][b][l];
        float4 r;
        r.x = (s0.x + s1.x) + (s2.x + s3.x);
        r.y = (s0.y + s1.y) + (s2.y + s3.y);
        r.z = (s0.z + s1.z) + (s2.z + s3.z);
        r.w = (s0.w + s1.w) + (s2.w + s3.w);
        *(float4*)&g_v_part[dch][b][blockIdx.x * 256 + l * 4] = r;
    }
}

// ---------------- K5r: hfinal = attn_out + bv + h_last ---------------------
__global__ void k5r_vreduce(const float* __restrict__ qkv_b) {
    int idx = blockIdx.x * 128 + threadIdx.x;   // 32 blocks
    int b = idx >> 10, j = idx & (ND - 1);
    float s = qkv_b[2048 + j];
#pragma unroll
    for (int c = 0; c < V_DSPLIT; c++) s += g_v_part[c][b][j];
    g_hfinal[b][j] = s + g_hlast[b][j];
}

// ---------------- K6: out partials = hfinal @ out_w (float4 weights) -------
__global__ void k6_out(const float* __restrict__ out_w) {
    __shared__ float  shf[NB][O_DCH];
    __shared__ float4 sred[4][NB][64];
    const int dc = blockIdx.y;
    const int tid = threadIdx.x;
    const int lane4 = tid & 63;       // col group: 4 cols
    const int dgrp  = tid >> 6;       // 0..3, 32 d-rows each
    for (int t = tid; t < NB * O_DCH; t += 256) {
        int b = t >> 7, d = t & (O_DCH - 1);
        shf[b][d] = g_hfinal[b][dc * O_DCH + d];
    }
    __syncthreads();
    const int v = blockIdx.x * 256 + lane4 * 4;
    const int d0 = dgrp * 32;
    float4 a0 = {0,0,0,0}, a1 = {0,0,0,0}, a2 = {0,0,0,0}, a3 = {0,0,0,0};
#pragma unroll 8
    for (int i = 0; i < 32; i++) {
        const int d = d0 + i;
        float4 w = *(const float4*)(out_w + (size_t)(dc * O_DCH + d) * NV + v);
        float h0 = shf[0][d], h1 = shf[1][d], h2 = shf[2][d], h3 = shf[3][d];
        a0.x = fmaf(h0, w.x, a0.x); a0.y = fmaf(h0, w.y, a0.y);
        a0.z = fmaf(h0, w.z, a0.z); a0.w = fmaf(h0, w.w, a0.w);
        a1.x = fmaf(h1, w.x, a1.x); a1.y = fmaf(h1, w.y, a1.y);
        a1.z = fmaf(h1, w.z, a1.z); a1.w = fmaf(h1, w.w, a1.w);
        a2.x = fmaf(h2, w.x, a2.x); a2.y = fmaf(h2, w.y, a2.y);
        a2.z = fmaf(h2, w.z, a2.z); a2.w = fmaf(h2, w.w, a2.w);
        a3.x = fmaf(h3, w.x, a3.x); a3.y = fmaf(h3, w.y, a3.y);
        a3.z = fmaf(h3, w.z, a3.z); a3.w = fmaf(h3, w.w, a3.w);
    }
    sred[dgrp][0][lane4] = a0;
    sred[dgrp][1][lane4] = a1;
    sred[dgrp][2][lane4] = a2;
    sred[dgrp][3][lane4] = a3;
    __syncthreads();
    {
        const int b = tid >> 6, l = tid & 63;   // 256 threads = 4 b x 64 lanes
        float4 s0 = sred[0][b][l], s1 = sred[1][b][l];
        float4 s2 = sred[2][b][l], s3 = sred[3][b][l];
        float4 r;
        r.x = (s0.x + s1.x) + (s2.x + s3.x);
        r.y = (s0.y + s1.y) + (s2.y + s3.y);
        r.z = (s0.z + s1.z) + (s2.z + s3.z);
        r.w = (s0.w + s1.w) + (s2.w + s3.w);
        *(float4*)&g_out_part[dc][b][blockIdx.x * 256 + l * 4] = r;
    }
}

// ---------------- K7: reduce partials + out_b -> d_out ---------------------
__global__ void k7_reduce(const float* __restrict__ out_b,
                          float* __restrict__ out) {
    const int v = blockIdx.x * 256 + threadIdx.x;
    const float ob = out_b[v];
#pragma unroll
    for (int b = 0; b < NB; b++) {
        float s = ob;
#pragma unroll
        for (int dc = 0; dc < O_DSPLIT; dc++) s += g_out_part[dc][b][v];
        out[b * NV + v] = s;
    }
}

extern "C" void kernel_launch(void* const* d_in, const int* in_sizes, int n_in,
                              void* d_out, int out_size) {
    const void*  x      = d_in[0];
    const float* embed  = (const float*)d_in[1];
    const float* qkv_w  = (const float*)d_in[2];
    const float* qkv_b  = (const float*)d_in[3];
    const float* out_w  = (const float*)d_in[4];
    const float* out_b  = (const float*)d_in[5];
    float* out = (float*)d_out;

    k1a_qpart<<<dim3(4, QK_DSPLIT), 256>>>(x, embed, qkv_w);
    k1ar_qreduce<<<32, 128>>>(qkv_b);
    k1b_qk<<<513, 256>>>(qkv_w, qkv_b);
    k2_logits<<<dim3(NS / 16, NB), 256>>>(x, embed);
    k3_softmax<<<NB, 1024>>>();
    k4_hbar<<<dim3(HB_CHUNK, NB), 256>>>(x, embed);
    k5a_vpart<<<dim3(4, V_DSPLIT), 256>>>(qkv_w);
    k5r_vreduce<<<32, 128>>>(qkv_b);
    k6_out<<<dim3(NV / 256, O_DSPLIT), 256>>>(out_w);
    k7_reduce<<<NV / 256, 256>>>(out_b, out);
}

// round 14
// speedup vs baseline: 1.0175x; 1.0175x over previous
#include <cuda_runtime.h>
#include <cstdint>

#define NB 4
#define NS 4096
#define ND 1024
#define NV 32000
#define ND3 3072

#define QK_DSPLIT 64
#define QK_DCH (ND / QK_DSPLIT)      // 16
#define HB_CHUNK 256
#define HB_ROWS (NS / HB_CHUNK)      // 16
#define V_DSPLIT 64
#define V_DCH (ND / V_DSPLIT)        // 16
#define O_DSPLIT 8
#define O_DCH (ND / O_DSPLIT)        // 128

// ---------------- scratch (device globals; no allocation allowed) ----------
__device__ __align__(16) float g_hlast[NB][ND];
__device__ __align__(16) float g_q_part[QK_DSPLIT][NB][ND];
__device__ __align__(16) float g_qlast[NB][ND];
__device__ __align__(16) float g_qk[NB][ND];          // pre-scaled by 1/32
__device__ float g_qbk[NB];                           // pre-scaled by 1/32
__device__ __align__(16) float g_logits[NB][NS];      // reused as attn
__device__ __align__(16) float g_hbar_part[HB_CHUNK][NB][ND];
__device__ __align__(16) float g_v_part[V_DSPLIT][NB][ND];
__device__ __align__(16) float g_hfinal[NB][ND];
__device__ __align__(16) float g_out_part[O_DSPLIT][NB][NV];

__device__ __forceinline__ int get_idx(const void* x, int i, bool is64) {
    if (is64) return (int)((const long long*)x)[i];
    return ((const int*)x)[i];
}

// ---------------- K1a: q_last partials = h_last @ Wq -----------------------
// Grid (4, 64): 256 blocks. 256 threads = 64 col-groups (float4) x 4 d-groups.
__global__ void k1a_qpart(const void* __restrict__ x,
                          const float* __restrict__ embed,
                          const float* __restrict__ qkv_w) {
    __shared__ float  sh[NB][QK_DCH];
    __shared__ float4 sred[4][NB][64];
    const int tid = threadIdx.x;
    // Inline int64 detection: first 64 odd int32 words are zero iff int64.
    int vdet = (tid < 64) ? ((const int*)x)[2 * tid + 1] : 0;
    const bool is64 = (__syncthreads_or(vdet) == 0);
    const int dch = blockIdx.y;
    if (tid < NB * QK_DCH) {
        int b = tid / QK_DCH, d = tid % QK_DCH;
        int row = get_idx(x, b * NS + NS - 1, is64);
        float v = embed[(size_t)row * ND + dch * QK_DCH + d];
        sh[b][d] = v;
        if (blockIdx.x == 0) g_hlast[b][dch * QK_DCH + d] = v;
    }
    __syncthreads();
    const int cg = tid & 63, dg = tid >> 6;
    const int j = blockIdx.x * 256 + cg * 4;
    float4 a0 = {0,0,0,0}, a1 = {0,0,0,0}, a2 = {0,0,0,0}, a3 = {0,0,0,0};
#pragma unroll
    for (int i = 0; i < 4; i++) {
        const int d = dg * 4 + i;
        float4 w = *(const float4*)(qkv_w + (size_t)(dch * QK_DCH + d) * ND3 + j);
        float h0 = sh[0][d], h1 = sh[1][d], h2 = sh[2][d], h3 = sh[3][d];
        a0.x = fmaf(h0, w.x, a0.x); a0.y = fmaf(h0, w.y, a0.y);
        a0.z = fmaf(h0, w.z, a0.z); a0.w = fmaf(h0, w.w, a0.w);
        a1.x = fmaf(h1, w.x, a1.x); a1.y = fmaf(h1, w.y, a1.y);
        a1.z = fmaf(h1, w.z, a1.z); a1.w = fmaf(h1, w.w, a1.w);
        a2.x = fmaf(h2, w.x, a2.x); a2.y = fmaf(h2, w.y, a2.y);
        a2.z = fmaf(h2, w.z, a2.z); a2.w = fmaf(h2, w.w, a2.w);
        a3.x = fmaf(h3, w.x, a3.x); a3.y = fmaf(h3, w.y, a3.y);
        a3.z = fmaf(h3, w.z, a3.z); a3.w = fmaf(h3, w.w, a3.w);
    }
    sred[dg][0][cg] = a0;
    sred[dg][1][cg] = a1;
    sred[dg][2][cg] = a2;
    sred[dg][3][cg] = a3;
    __syncthreads();
    {
        const int b = tid >> 6, l = tid & 63;
        float4 s0 = sred[0][b][l], s1 = sred[1][b][l];
        float4 s2 = sred[2][b][l], s3 = sred[3][b][l];
        float4 r;
        r.x = (s0.x + s1.x) + (s2.x + s3.x);
        r.y = (s0.y + s1.y) + (s2.y + s3.y);
        r.z = (s0.z + s1.z) + (s2.z + s3.z);
        r.w = (s0.w + s1.w) + (s2.w + s3.w);
        *(float4*)&g_q_part[dch][b][blockIdx.x * 256 + l * 4] = r;
    }
}

// ---------------- K1ar: reduce partials + bias -> q_last -------------------
__global__ void k1ar_qreduce(const float* __restrict__ qkv_b) {
    int idx = blockIdx.x * 128 + threadIdx.x;     // 32 blocks
    int b = idx >> 10, j = idx & (ND - 1);
    float s = qkv_b[j];
#pragma unroll
    for (int c = 0; c < QK_DSPLIT; c++) s += g_q_part[c][b][j];
    g_qlast[b][j] = s;
}

// ---------------- K1b: qk[j] = Wk-row(j) . q_last --------------------------
__global__ void k1b_qk(const float* __restrict__ qkv_w,
                       const float* __restrict__ qkv_b) {
    __shared__ float4 sq[NB][256];    // qlast, 16 KB
    __shared__ float red[2][4][NB];
    const int tid = threadIdx.x, warp = tid >> 5, lane = tid & 31;
    const float kInv = 0.03125f;                  // 1/sqrt(1024)
    if (blockIdx.x < 512) {
        const int rloc = warp >> 2;               // 0..1
        const int quad = warp & 3;                // 0..3
        const int j = blockIdx.x * 2 + rloc;
        const float4* wrow = (const float4*)(qkv_w + (size_t)j * ND3 + ND);
        const int p0 = quad * 64 + lane;
        const int p1 = quad * 64 + 32 + lane;
        float4 w0 = wrow[p0];
        float4 w1 = wrow[p1];
        {
            float4 t0 = ((const float4*)g_qlast[0])[tid];
            float4 t1 = ((const float4*)g_qlast[1])[tid];
            float4 t2 = ((const float4*)g_qlast[2])[tid];
            float4 t3 = ((const float4*)g_qlast[3])[tid];
            sq[0][tid] = t0; sq[1][tid] = t1; sq[2][tid] = t2; sq[3][tid] = t3;
        }
        __syncthreads();
        float a0, a1, a2, a3;
        {
            float4 q0 = sq[0][p0], q1 = sq[1][p0], q2 = sq[2][p0], q3 = sq[3][p0];
            a0 = fmaf(w0.x, q0.x, fmaf(w0.y, q0.y, fmaf(w0.z, q0.z, w0.w * q0.w)));
            a1 = fmaf(w0.x, q1.x, fmaf(w0.y, q1.y, fmaf(w0.z, q1.z, w0.w * q1.w)));
            a2 = fmaf(w0.x, q2.x, fmaf(w0.y, q2.y, fmaf(w0.z, q2.z, w0.w * q2.w)));
            a3 = fmaf(w0.x, q3.x, fmaf(w0.y, q3.y, fmaf(w0.z, q3.z, w0.w * q3.w)));
        }
        {
            float4 q0 = sq[0][p1], q1 = sq[1][p1], q2 = sq[2][p1], q3 = sq[3][p1];
            a0 = fmaf(w1.x, q0.x, fmaf(w1.y, q0.y, fmaf(w1.z, q0.z, fmaf(w1.w, q0.w, a0))));
            a1 = fmaf(w1.x, q1.x, fmaf(w1.y, q1.y, fmaf(w1.z, q1.z, fmaf(w1.w, q1.w, a1))));
            a2 = fmaf(w1.x, q2.x, fmaf(w1.y, q2.y, fmaf(w1.z, q2.z, fmaf(w1.w, q2.w, a2))));
            a3 = fmaf(w1.x, q3.x, fmaf(w1.y, q3.y, fmaf(w1.z, q3.z, fmaf(w1.w, q3.w, a3))));
        }
#pragma unroll
        for (int o = 16; o > 0; o >>= 1) {
            a0 += __shfl_xor_sync(0xffffffffu, a0, o);
            a1 += __shfl_xor_sync(0xffffffffu, a1, o);
            a2 += __shfl_xor_sync(0xffffffffu, a2, o);
            a3 += __shfl_xor_sync(0xffffffffu, a3, o);
        }
        if (lane == 0) {
            red[rloc][quad][0] = a0; red[rloc][quad][1] = a1;
            red[rloc][quad][2] = a2; red[rloc][quad][3] = a3;
        }
        __syncthreads();
        if (tid < 8) {
            int r = tid >> 2, b = tid & 3;
            float s = red[r][0][b] + red[r][1][b] + red[r][2][b] + red[r][3][b];
            g_qk[b][blockIdx.x * 2 + r] = s * kInv;
        }
    } else {
        if (warp < NB) {
            const float4* bk = (const float4*)(qkv_b + ND);
            const float4* q  = (const float4*)g_qlast[warp];
            float a = 0.f;
#pragma unroll
            for (int it = 0; it < 8; it++) {
                int p = lane + 32 * it;
                float4 w = bk[p];
                float4 qq = q[p];
                a = fmaf(w.x, qq.x, fmaf(w.y, qq.y, fmaf(w.z, qq.z, fmaf(w.w, qq.w, a))));
            }
#pragma unroll
            for (int o = 16; o > 0; o >>= 1) a += __shfl_xor_sync(0xffffffffu, a, o);
            if (lane == 0) g_qbk[warp] = a * kInv;
        }
    }
}

// ---------------- K2: logits[b][s] = embed[x[b,s]] . qk[b] + qbk[b] --------
// Front-batched loads: all 16 float4 (2 rows x 8) loaded into registers
// BEFORE any FMA. __launch_bounds__(256,3) -> reg ceiling 85 so ptxas keeps
// the full batch in flight (regs=40 previously serialized it).
__global__ void __launch_bounds__(256, 3)
k2_logits(const void* __restrict__ x,
          const float* __restrict__ embed) {
    __shared__ float4 sqk[256];
    const int b = blockIdx.y;
    const int tid = threadIdx.x;
    int vdet = (tid < 64) ? ((const int*)x)[2 * tid + 1] : 0;
    sqk[tid] = ((const float4*)g_qk[b])[tid];
    const bool is64 = (__syncthreads_or(vdet) == 0);   // also the sqk barrier
    const int warp = tid >> 5, lane = tid & 31;
    const int s0 = blockIdx.x * 16 + warp * 2;
    const int rowA = get_idx(x, b * NS + s0, is64);
    const int rowB = get_idx(x, b * NS + s0 + 1, is64);
    const float4* eA = (const float4*)(embed + (size_t)rowA * ND);
    const float4* eB = (const float4*)(embed + (size_t)rowB * ND);
    float4 ra[8], rb[8];
#pragma unroll
    for (int it = 0; it < 8; it++) {
        ra[it] = eA[lane + 32 * it];
        rb[it] = eB[lane + 32 * it];
    }
    float a = 0.f, c = 0.f;
#pragma unroll
    for (int it = 0; it < 8; it++) {
        float4 q = sqk[lane + 32 * it];
        a = fmaf(ra[it].x, q.x, fmaf(ra[it].y, q.y, fmaf(ra[it].z, q.z, fmaf(ra[it].w, q.w, a))));
        c = fmaf(rb[it].x, q.x, fmaf(rb[it].y, q.y, fmaf(rb[it].z, q.z, fmaf(rb[it].w, q.w, c))));
    }
#pragma unroll
    for (int o = 16; o > 0; o >>= 1) {
        a += __shfl_xor_sync(0xffffffffu, a, o);
        c += __shfl_xor_sync(0xffffffffu, c, o);
    }
    if (lane == 0) {
        float qb = g_qbk[b];
        g_logits[b][s0]     = a + qb;
        g_logits[b][s0 + 1] = c + qb;
    }
}

// ---------------- K3: softmax over 4096 keys, in place ---------------------
__global__ void k3_softmax() {
    __shared__ float red[32];
    __shared__ float bcast;
    const int b = blockIdx.x, t = threadIdx.x;
    const int lane = t & 31, warp = t >> 5;
    float l0 = g_logits[b][t];
    float l1 = g_logits[b][t + 1024];
    float l2 = g_logits[b][t + 2048];
    float l3 = g_logits[b][t + 3072];
    float m = fmaxf(fmaxf(l0, l1), fmaxf(l2, l3));
#pragma unroll
    for (int o = 16; o > 0; o >>= 1) m = fmaxf(m, __shfl_xor_sync(0xffffffffu, m, o));
    if (lane == 0) red[warp] = m;
    __syncthreads();
    if (t < 32) {
        float mm = red[t];
#pragma unroll
        for (int o = 16; o > 0; o >>= 1) mm = fmaxf(mm, __shfl_xor_sync(0xffffffffu, mm, o));
        if (t == 0) bcast = mm;
    }
    __syncthreads();
    const float M = bcast;
    float e0 = expf(l0 - M), e1 = expf(l1 - M), e2 = expf(l2 - M), e3 = expf(l3 - M);
    float s = (e0 + e1) + (e2 + e3);
#pragma unroll
    for (int o = 16; o > 0; o >>= 1) s += __shfl_xor_sync(0xffffffffu, s, o);
    __syncthreads();
    if (lane == 0) red[warp] = s;
    __syncthreads();
    if (t < 32) {
        float ss = red[t];
#pragma unroll
        for (int o = 16; o > 0; o >>= 1) ss += __shfl_xor_sync(0xffffffffu, ss, o);
        if (t == 0) bcast = ss;
    }
    __syncthreads();
    const float inv = 1.0f / bcast;
    g_logits[b][t]        = e0 * inv;
    g_logits[b][t + 1024] = e1 * inv;
    g_logits[b][t + 2048] = e2 * inv;
    g_logits[b][t + 3072] = e3 * inv;
}

// ---------------- K4: hbar partials = sum_s attn[b,s] * embed[x[b,s]] ------
__global__ void k4_hbar(const void* __restrict__ x,
                        const float* __restrict__ embed) {
    const int c = blockIdx.x, b = blockIdx.y;
    const int t = threadIdx.x;
    int vdet = (t < 64) ? ((const int*)x)[2 * t + 1] : 0;
    const bool is64 = (__syncthreads_or(vdet) == 0);
    float4 acc = make_float4(0.f, 0.f, 0.f, 0.f);
    const int s0 = c * HB_ROWS;
#pragma unroll 8
    for (int r = 0; r < HB_ROWS; r++) {
        int s = s0 + r;
        float w = g_logits[b][s];
        int row = get_idx(x, b * NS + s, is64);
        float4 e = ((const float4*)(embed + (size_t)row * ND))[t];
        acc.x = fmaf(w, e.x, acc.x);
        acc.y = fmaf(w, e.y, acc.y);
        acc.z = fmaf(w, e.z, acc.z);
        acc.w = fmaf(w, e.w, acc.w);
    }
    ((float4*)g_hbar_part[c][b])[t] = acc;
}

// ---------------- K5a: v partials = hbar @ Wv ------------------------------
__global__ void k5a_vpart(const float* __restrict__ qkv_w) {
    __shared__ float  psum[4][NB][V_DCH];
    __shared__ float  sh[NB][V_DCH];
    __shared__ float4 sred[4][NB][64];
    const int dch = blockIdx.y;
    const int tid = threadIdx.x;
    {   // preamble: sh[b][d] = sum_c hbar_part[c][b][dch*16+d], 256-way
        const int cgrp = tid >> 6;            // 0..3 (64 chunks each)
        const int rem = tid & 63;
        const int b = rem >> 4, d = rem & 15;
        float s = 0.f;
#pragma unroll 8
        for (int k = 0; k < HB_CHUNK / 4; k++)
            s += g_hbar_part[cgrp * (HB_CHUNK / 4) + k][b][dch * V_DCH + d];
        psum[cgrp][b][d] = s;
        __syncthreads();
        if (tid < NB * V_DCH) {
            int bb = tid >> 4, dd = tid & 15;
            sh[bb][dd] = (psum[0][bb][dd] + psum[1][bb][dd])
                       + (psum[2][bb][dd] + psum[3][bb][dd]);
        }
        __syncthreads();
    }
    const int cg = tid & 63, dg = tid >> 6;
    const int j = blockIdx.x * 256 + cg * 4;
    float4 a0 = {0,0,0,0}, a1 = {0,0,0,0}, a2 = {0,0,0,0}, a3 = {0,0,0,0};
#pragma unroll
    for (int i = 0; i < 4; i++) {
        const int d = dg * 4 + i;
        float4 w = *(const float4*)(qkv_w + (size_t)(dch * V_DCH + d) * ND3 + 2048 + j);
        float h0 = sh[0][d], h1 = sh[1][d], h2 = sh[2][d], h3 = sh[3][d];
        a0.x = fmaf(h0, w.x, a0.x); a0.y = fmaf(h0, w.y, a0.y);
        a0.z = fmaf(h0, w.z, a0.z); a0.w = fmaf(h0, w.w, a0.w);
        a1.x = fmaf(h1, w.x, a1.x); a1.y = fmaf(h1, w.y, a1.y);
        a1.z = fmaf(h1, w.z, a1.z); a1.w = fmaf(h1, w.w, a1.w);
        a2.x = fmaf(h2, w.x, a2.x); a2.y = fmaf(h2, w.y, a2.y);
        a2.z = fmaf(h2, w.z, a2.z); a2.w = fmaf(h2, w.w, a2.w);
        a3.x = fmaf(h3, w.x, a3.x); a3.y = fmaf(h3, w.y, a3.y);
        a3.z = fmaf(h3, w.z, a3.z); a3.w = fmaf(h3, w.w, a3.w);
    }
    sred[dg][0][cg] = a0;
    sred[dg][1][cg] = a1;
    sred[dg][2][cg] = a2;
    sred[dg][3][cg] = a3;
    __syncthreads();
    {
        const int b = tid >> 6, l = tid & 63;
        float4 s0 = sred[0][b][l], s1 = sred[1][b][l];
        float4 s2 = sred[2][b][l], s3 = sred[3][b][l];
        float4 r;
        r.x = (s0.x + s1.x) + (s2.x + s3.x);
        r.y = (s0.y + s1.y) + (s2.y + s3.y);
        r.z = (s0.z + s1.z) + (s2.z + s3.z);
        r.w = (s0.w + s1.w) + (s2.w + s3.w);
        *(float4*)&g_v_part[dch][b][blockIdx.x * 256 + l * 4] = r;
    }
}

// ---------------- K5r: hfinal = attn_out + bv + h_last ---------------------
__global__ void k5r_vreduce(const float* __restrict__ qkv_b) {
    int idx = blockIdx.x * 128 + threadIdx.x;   // 32 blocks
    int b = idx >> 10, j = idx & (ND - 1);
    float s = qkv_b[2048 + j];
#pragma unroll
    for (int c = 0; c < V_DSPLIT; c++) s += g_v_part[c][b][j];
    g_hfinal[b][j] = s + g_hlast[b][j];
}

// ---------------- K6: out partials = hfinal @ out_w (float4 weights) -------
__global__ void k6_out(const float* __restrict__ out_w) {
    __shared__ float  shf[NB][O_DCH];
    __shared__ float4 sred[4][NB][64];
    const int dc = blockIdx.y;
    const int tid = threadIdx.x;
    const int lane4 = tid & 63;       // col group: 4 cols
    const int dgrp  = tid >> 6;       // 0..3, 32 d-rows each
    for (int t = tid; t < NB * O_DCH; t += 256) {
        int b = t >> 7, d = t & (O_DCH - 1);
        shf[b][d] = g_hfinal[b][dc * O_DCH + d];
    }
    __syncthreads();
    const int v = blockIdx.x * 256 + lane4 * 4;
    const int d0 = dgrp * 32;
    float4 a0 = {0,0,0,0}, a1 = {0,0,0,0}, a2 = {0,0,0,0}, a3 = {0,0,0,0};
#pragma unroll 8
    for (int i = 0; i < 32; i++) {
        const int d = d0 + i;
        float4 w = *(const float4*)(out_w + (size_t)(dc * O_DCH + d) * NV + v);
        float h0 = shf[0][d], h1 = shf[1][d], h2 = shf[2][d], h3 = shf[3][d];
        a0.x = fmaf(h0, w.x, a0.x); a0.y = fmaf(h0, w.y, a0.y);
        a0.z = fmaf(h0, w.z, a0.z); a0.w = fmaf(h0, w.w, a0.w);
        a1.x = fmaf(h1, w.x, a1.x); a1.y = fmaf(h1, w.y, a1.y);
        a1.z = fmaf(h1, w.z, a1.z); a1.w = fmaf(h1, w.w, a1.w);
        a2.x = fmaf(h2, w.x, a2.x); a2.y = fmaf(h2, w.y, a2.y);
        a2.z = fmaf(h2, w.z, a2.z); a2.w = fmaf(h2, w.w, a2.w);
        a3.x = fmaf(h3, w.x, a3.x); a3.y = fmaf(h3, w.y, a3.y);
        a3.z = fmaf(h3, w.z, a3.z); a3.w = fmaf(h3, w.w, a3.w);
    }
    sred[dgrp][0][lane4] = a0;
    sred[dgrp][1][lane4] = a1;
    sred[dgrp][2][lane4] = a2;
    sred[dgrp][3][lane4] = a3;
    __syncthreads();
    {
        const int b = tid >> 6, l = tid & 63;   // 256 threads = 4 b x 64 lanes
        float4 s0 = sred[0][b][l], s1 = sred[1][b][l];
        float4 s2 = sred[2][b][l], s3 = sred[3][b][l];
        float4 r;
        r.x = (s0.x + s1.x) + (s2.x + s3.x);
        r.y = (s0.y + s1.y) + (s2.y + s3.y);
        r.z = (s0.z + s1.z) + (s2.z + s3.z);
        r.w = (s0.w + s1.w) + (s2.w + s3.w);
        *(float4*)&g_out_part[dc][b][blockIdx.x * 256 + l * 4] = r;
    }
}

// ---------------- K7: reduce partials + out_b -> d_out ---------------------
__global__ void k7_reduce(const float* __restrict__ out_b,
                          float* __restrict__ out) {
    const int v = blockIdx.x * 256 + threadIdx.x;
    const float ob = out_b[v];
#pragma unroll
    for (int b = 0; b < NB; b++) {
        float s = ob;
#pragma unroll
        for (int dc = 0; dc < O_DSPLIT; dc++) s += g_out_part[dc][b][v];
        out[b * NV + v] = s;
    }
}

extern "C" void kernel_launch(void* const* d_in, const int* in_sizes, int n_in,
                              void* d_out, int out_size) {
    const void*  x      = d_in[0];
    const float* embed  = (const float*)d_in[1];
    const float* qkv_w  = (const float*)d_in[2];
    const float* qkv_b  = (const float*)d_in[3];
    const float* out_w  = (const float*)d_in[4];
    const float* out_b  = (const float*)d_in[5];
    float* out = (float*)d_out;

    k1a_qpart<<<dim3(4, QK_DSPLIT), 256>>>(x, embed, qkv_w);
    k1ar_qreduce<<<32, 128>>>(qkv_b);
    k1b_qk<<<513, 256>>>(qkv_w, qkv_b);
    k2_logits<<<dim3(NS / 16, NB), 256>>>(x, embed);
    k3_softmax<<<NB, 1024>>>();
    k4_hbar<<<dim3(HB_CHUNK, NB), 256>>>(x, embed);
    k5a_vpart<<<dim3(4, V_DSPLIT), 256>>>(qkv_w);
    k5r_vreduce<<<32, 128>>>(qkv_b);
    k6_out<<<dim3(NV / 256, O_DSPLIT), 256>>>(out_w);
    k7_reduce<<<NV / 256, 256>>>(out_b, out);
}

// round 15
// speedup vs baseline: 1.0315x; 1.0137x over previous
#include <cuda_runtime.h>
#include <cstdint>

#define NB 4
#define NS 4096
#define ND 1024
#define NV 32000
#define ND3 3072

#define QK_DSPLIT 64
#define QK_DCH (ND / QK_DSPLIT)      // 16
#define HB_CHUNK 256
#define HB_ROWS (NS / HB_CHUNK)      // 16
#define V_DSPLIT 64
#define V_DCH (ND / V_DSPLIT)        // 16
#define O_DSPLIT 8
#define O_DCH (ND / O_DSPLIT)        // 128

// ---------------- scratch (device globals; no allocation allowed) ----------
__device__ __align__(16) float g_hlast[NB][ND];
__device__ __align__(16) float g_qlast[NB][ND];       // accum: init bias_q
__device__ __align__(16) float g_qk[NB][ND];          // pre-scaled by 1/32
__device__ float g_qbk[NB];                           // pre-scaled by 1/32
__device__ __align__(16) float g_logits[NB][NS];      // reused as attn
__device__ __align__(16) float g_hbar_part[HB_CHUNK][NB][ND];
__device__ __align__(16) float g_hfinal[NB][ND];      // accum: init bias_v

__device__ __forceinline__ int get_idx(const void* x, int i, bool is64) {
    if (is64) return (int)((const long long*)x)[i];
    return ((const int*)x)[i];
}

// ---------------- KINIT: initialize accumulators ---------------------------
// 125 blocks x 256: out = out_b broadcast; blocks 0-15: qlast=bq, hfinal=bv.
__global__ void kinit(const float* __restrict__ qkv_b,
                      const float* __restrict__ out_b,
                      float* __restrict__ out) {
    const int v = blockIdx.x * 256 + threadIdx.x;   // 0..31999
    const float ob = out_b[v];
    out[0 * NV + v] = ob;
    out[1 * NV + v] = ob;
    out[2 * NV + v] = ob;
    out[3 * NV + v] = ob;
    if (blockIdx.x < 16) {
        int idx = blockIdx.x * 256 + threadIdx.x;   // 0..4095
        int b = idx >> 10, j = idx & (ND - 1);
        g_qlast[b][j]  = qkv_b[j];
        g_hfinal[b][j] = qkv_b[2048 + j];
    }
}

// ---------------- K1a: q_last partials -> atomicAdd into g_qlast -----------
// Grid (4, 64): 256 blocks. 256 threads = 64 col-groups (float4) x 4 d-groups.
__global__ void k1a_qpart(const void* __restrict__ x,
                          const float* __restrict__ embed,
                          const float* __restrict__ qkv_w) {
    __shared__ float  sh[NB][QK_DCH];
    __shared__ float4 sred[4][NB][64];
    const int tid = threadIdx.x;
    // Inline int64 detection: first 64 odd int32 words are zero iff int64.
    int vdet = (tid < 64) ? ((const int*)x)[2 * tid + 1] : 0;
    const bool is64 = (__syncthreads_or(vdet) == 0);
    const int dch = blockIdx.y;
    if (tid < NB * QK_DCH) {
        int b = tid / QK_DCH, d = tid % QK_DCH;
        int row = get_idx(x, b * NS + NS - 1, is64);
        float v = embed[(size_t)row * ND + dch * QK_DCH + d];
        sh[b][d] = v;
        if (blockIdx.x == 0) g_hlast[b][dch * QK_DCH + d] = v;
    }
    __syncthreads();
    const int cg = tid & 63, dg = tid >> 6;
    const int j = blockIdx.x * 256 + cg * 4;
    float4 a0 = {0,0,0,0}, a1 = {0,0,0,0}, a2 = {0,0,0,0}, a3 = {0,0,0,0};
#pragma unroll
    for (int i = 0; i < 4; i++) {
        const int d = dg * 4 + i;
        float4 w = *(const float4*)(qkv_w + (size_t)(dch * QK_DCH + d) * ND3 + j);
        float h0 = sh[0][d], h1 = sh[1][d], h2 = sh[2][d], h3 = sh[3][d];
        a0.x = fmaf(h0, w.x, a0.x); a0.y = fmaf(h0, w.y, a0.y);
        a0.z = fmaf(h0, w.z, a0.z); a0.w = fmaf(h0, w.w, a0.w);
        a1.x = fmaf(h1, w.x, a1.x); a1.y = fmaf(h1, w.y, a1.y);
        a1.z = fmaf(h1, w.z, a1.z); a1.w = fmaf(h1, w.w, a1.w);
        a2.x = fmaf(h2, w.x, a2.x); a2.y = fmaf(h2, w.y, a2.y);
        a2.z = fmaf(h2, w.z, a2.z); a2.w = fmaf(h2, w.w, a2.w);
        a3.x = fmaf(h3, w.x, a3.x); a3.y = fmaf(h3, w.y, a3.y);
        a3.z = fmaf(h3, w.z, a3.z); a3.w = fmaf(h3, w.w, a3.w);
    }
    sred[dg][0][cg] = a0;
    sred[dg][1][cg] = a1;
    sred[dg][2][cg] = a2;
    sred[dg][3][cg] = a3;
    __syncthreads();
    {
        const int b = tid >> 6, l = tid & 63;
        float4 s0 = sred[0][b][l], s1 = sred[1][b][l];
        float4 s2 = sred[2][b][l], s3 = sred[3][b][l];
        float* dst = &g_qlast[b][blockIdx.x * 256 + l * 4];
        atomicAdd(dst + 0, (s0.x + s1.x) + (s2.x + s3.x));
        atomicAdd(dst + 1, (s0.y + s1.y) + (s2.y + s3.y));
        atomicAdd(dst + 2, (s0.z + s1.z) + (s2.z + s3.z));
        atomicAdd(dst + 3, (s0.w + s1.w) + (s2.w + s3.w));
    }
}

// ---------------- K1b: qk[j] = Wk-row(j) . q_last --------------------------
__global__ void k1b_qk(const float* __restrict__ qkv_w,
                       const float* __restrict__ qkv_b) {
    __shared__ float4 sq[NB][256];    // qlast, 16 KB
    __shared__ float red[2][4][NB];
    const int tid = threadIdx.x, warp = tid >> 5, lane = tid & 31;
    const float kInv = 0.03125f;                  // 1/sqrt(1024)
    if (blockIdx.x < 512) {
        const int rloc = warp >> 2;               // 0..1
        const int quad = warp & 3;                // 0..3
        const int j = blockIdx.x * 2 + rloc;
        const float4* wrow = (const float4*)(qkv_w + (size_t)j * ND3 + ND);
        const int p0 = quad * 64 + lane;
        const int p1 = quad * 64 + 32 + lane;
        float4 w0 = wrow[p0];
        float4 w1 = wrow[p1];
        {
            float4 t0 = ((const float4*)g_qlast[0])[tid];
            float4 t1 = ((const float4*)g_qlast[1])[tid];
            float4 t2 = ((const float4*)g_qlast[2])[tid];
            float4 t3 = ((const float4*)g_qlast[3])[tid];
            sq[0][tid] = t0; sq[1][tid] = t1; sq[2][tid] = t2; sq[3][tid] = t3;
        }
        __syncthreads();
        float a0, a1, a2, a3;
        {
            float4 q0 = sq[0][p0], q1 = sq[1][p0], q2 = sq[2][p0], q3 = sq[3][p0];
            a0 = fmaf(w0.x, q0.x, fmaf(w0.y, q0.y, fmaf(w0.z, q0.z, w0.w * q0.w)));
            a1 = fmaf(w0.x, q1.x, fmaf(w0.y, q1.y, fmaf(w0.z, q1.z, w0.w * q1.w)));
            a2 = fmaf(w0.x, q2.x, fmaf(w0.y, q2.y, fmaf(w0.z, q2.z, w0.w * q2.w)));
            a3 = fmaf(w0.x, q3.x, fmaf(w0.y, q3.y, fmaf(w0.z, q3.z, w0.w * q3.w)));
        }
        {
            float4 q0 = sq[0][p1], q1 = sq[1][p1], q2 = sq[2][p1], q3 = sq[3][p1];
            a0 = fmaf(w1.x, q0.x, fmaf(w1.y, q0.y, fmaf(w1.z, q0.z, fmaf(w1.w, q0.w, a0))));
            a1 = fmaf(w1.x, q1.x, fmaf(w1.y, q1.y, fmaf(w1.z, q1.z, fmaf(w1.w, q1.w, a1))));
            a2 = fmaf(w1.x, q2.x, fmaf(w1.y, q2.y, fmaf(w1.z, q2.z, fmaf(w1.w, q2.w, a2))));
            a3 = fmaf(w1.x, q3.x, fmaf(w1.y, q3.y, fmaf(w1.z, q3.z, fmaf(w1.w, q3.w, a3))));
        }
#pragma unroll
        for (int o = 16; o > 0; o >>= 1) {
            a0 += __shfl_xor_sync(0xffffffffu, a0, o);
            a1 += __shfl_xor_sync(0xffffffffu, a1, o);
            a2 += __shfl_xor_sync(0xffffffffu, a2, o);
            a3 += __shfl_xor_sync(0xffffffffu, a3, o);
        }
        if (lane == 0) {
            red[rloc][quad][0] = a0; red[rloc][quad][1] = a1;
            red[rloc][quad][2] = a2; red[rloc][quad][3] = a3;
        }
        __syncthreads();
        if (tid < 8) {
            int r = tid >> 2, b = tid & 3;
            float s = red[r][0][b] + red[r][1][b] + red[r][2][b] + red[r][3][b];
            g_qk[b][blockIdx.x * 2 + r] = s * kInv;
        }
    } else {
        if (warp < NB) {
            const float4* bk = (const float4*)(qkv_b + ND);
            const float4* q  = (const float4*)g_qlast[warp];
            float a = 0.f;
#pragma unroll
            for (int it = 0; it < 8; it++) {
                int p = lane + 32 * it;
                float4 w = bk[p];
                float4 qq = q[p];
                a = fmaf(w.x, qq.x, fmaf(w.y, qq.y, fmaf(w.z, qq.z, fmaf(w.w, qq.w, a))));
            }
#pragma unroll
            for (int o = 16; o > 0; o >>= 1) a += __shfl_xor_sync(0xffffffffu, a, o);
            if (lane == 0) g_qbk[warp] = a * kInv;
        }
    }
}

// ---------------- K2: logits[b][s] = embed[x[b,s]] . qk[b] + qbk[b] --------
__global__ void __launch_bounds__(256, 3)
k2_logits(const void* __restrict__ x,
          const float* __restrict__ embed) {
    __shared__ float4 sqk[256];
    const int b = blockIdx.y;
    const int tid = threadIdx.x;
    int vdet = (tid < 64) ? ((const int*)x)[2 * tid + 1] : 0;
    sqk[tid] = ((const float4*)g_qk[b])[tid];
    const bool is64 = (__syncthreads_or(vdet) == 0);   // also the sqk barrier
    const int warp = tid >> 5, lane = tid & 31;
    const int s0 = blockIdx.x * 16 + warp * 2;
    const int rowA = get_idx(x, b * NS + s0, is64);
    const int rowB = get_idx(x, b * NS + s0 + 1, is64);
    const float4* eA = (const float4*)(embed + (size_t)rowA * ND);
    const float4* eB = (const float4*)(embed + (size_t)rowB * ND);
    float4 ra[8], rb[8];
#pragma unroll
    for (int it = 0; it < 8; it++) {
        ra[it] = eA[lane + 32 * it];
        rb[it] = eB[lane + 32 * it];
    }
    float a = 0.f, c = 0.f;
#pragma unroll
    for (int it = 0; it < 8; it++) {
        float4 q = sqk[lane + 32 * it];
        a = fmaf(ra[it].x, q.x, fmaf(ra[it].y, q.y, fmaf(ra[it].z, q.z, fmaf(ra[it].w, q.w, a))));
        c = fmaf(rb[it].x, q.x, fmaf(rb[it].y, q.y, fmaf(rb[it].z, q.z, fmaf(rb[it].w, q.w, c))));
    }
#pragma unroll
    for (int o = 16; o > 0; o >>= 1) {
        a += __shfl_xor_sync(0xffffffffu, a, o);
        c += __shfl_xor_sync(0xffffffffu, c, o);
    }
    if (lane == 0) {
        float qb = g_qbk[b];
        g_logits[b][s0]     = a + qb;
        g_logits[b][s0 + 1] = c + qb;
    }
}

// ---------------- K3: softmax over 4096 keys, in place ---------------------
__global__ void k3_softmax() {
    __shared__ float red[32];
    __shared__ float bcast;
    const int b = blockIdx.x, t = threadIdx.x;
    const int lane = t & 31, warp = t >> 5;
    float l0 = g_logits[b][t];
    float l1 = g_logits[b][t + 1024];
    float l2 = g_logits[b][t + 2048];
    float l3 = g_logits[b][t + 3072];
    float m = fmaxf(fmaxf(l0, l1), fmaxf(l2, l3));
#pragma unroll
    for (int o = 16; o > 0; o >>= 1) m = fmaxf(m, __shfl_xor_sync(0xffffffffu, m, o));
    if (lane == 0) red[warp] = m;
    __syncthreads();
    if (t < 32) {
        float mm = red[t];
#pragma unroll
        for (int o = 16; o > 0; o >>= 1) mm = fmaxf(mm, __shfl_xor_sync(0xffffffffu, mm, o));
        if (t == 0) bcast = mm;
    }
    __syncthreads();
    const float M = bcast;
    float e0 = expf(l0 - M), e1 = expf(l1 - M), e2 = expf(l2 - M), e3 = expf(l3 - M);
    float s = (e0 + e1) + (e2 + e3);
#pragma unroll
    for (int o = 16; o > 0; o >>= 1) s += __shfl_xor_sync(0xffffffffu, s, o);
    __syncthreads();
    if (lane == 0) red[warp] = s;
    __syncthreads();
    if (t < 32) {
        float ss = red[t];
#pragma unroll
        for (int o = 16; o > 0; o >>= 1) ss += __shfl_xor_sync(0xffffffffu, ss, o);
        if (t == 0) bcast = ss;
    }
    __syncthreads();
    const float inv = 1.0f / bcast;
    g_logits[b][t]        = e0 * inv;
    g_logits[b][t + 1024] = e1 * inv;
    g_logits[b][t + 2048] = e2 * inv;
    g_logits[b][t + 3072] = e3 * inv;
}

// ---------------- K4: hbar partials = sum_s attn[b,s] * embed[x[b,s]] ------
__global__ void k4_hbar(const void* __restrict__ x,
                        const float* __restrict__ embed) {
    const int c = blockIdx.x, b = blockIdx.y;
    const int t = threadIdx.x;
    int vdet = (t < 64) ? ((const int*)x)[2 * t + 1] : 0;
    const bool is64 = (__syncthreads_or(vdet) == 0);
    float4 acc = make_float4(0.f, 0.f, 0.f, 0.f);
    const int s0 = c * HB_ROWS;
#pragma unroll 8
    for (int r = 0; r < HB_ROWS; r++) {
        int s = s0 + r;
        float w = g_logits[b][s];
        int row = get_idx(x, b * NS + s, is64);
        float4 e = ((const float4*)(embed + (size_t)row * ND))[t];
        acc.x = fmaf(w, e.x, acc.x);
        acc.y = fmaf(w, e.y, acc.y);
        acc.z = fmaf(w, e.z, acc.z);
        acc.w = fmaf(w, e.w, acc.w);
    }
    ((float4*)g_hbar_part[c][b])[t] = acc;
}

// ---------------- K5a: v partials = hbar @ Wv -> atomicAdd g_hfinal --------
__global__ void k5a_vpart(const float* __restrict__ qkv_w) {
    __shared__ float  psum[4][NB][V_DCH];
    __shared__ float  sh[NB][V_DCH];
    __shared__ float4 sred[4][NB][64];
    const int dch = blockIdx.y;
    const int tid = threadIdx.x;
    {   // preamble: sh[b][d] = sum_c hbar_part[c][b][dch*16+d], 256-way
        const int cgrp = tid >> 6;            // 0..3 (64 chunks each)
        const int rem = tid & 63;
        const int b = rem >> 4, d = rem & 15;
        float s = 0.f;
#pragma unroll 8
        for (int k = 0; k < HB_CHUNK / 4; k++)
            s += g_hbar_part[cgrp * (HB_CHUNK / 4) + k][b][dch * V_DCH + d];
        psum[cgrp][b][d] = s;
        __syncthreads();
        if (tid < NB * V_DCH) {
            int bb = tid >> 4, dd = tid & 15;
            sh[bb][dd] = (psum[0][bb][dd] + psum[1][bb][dd])
                       + (psum[2][bb][dd] + psum[3][bb][dd]);
        }
        __syncthreads();
    }
    const int cg = tid & 63, dg = tid >> 6;
    const int j = blockIdx.x * 256 + cg * 4;
    float4 a0 = {0,0,0,0}, a1 = {0,0,0,0}, a2 = {0,0,0,0}, a3 = {0,0,0,0};
#pragma unroll
    for (int i = 0; i < 4; i++) {
        const int d = dg * 4 + i;
        float4 w = *(const float4*)(qkv_w + (size_t)(dch * V_DCH + d) * ND3 + 2048 + j);
        float h0 = sh[0][d], h1 = sh[1][d], h2 = sh[2][d], h3 = sh[3][d];
        a0.x = fmaf(h0, w.x, a0.x); a0.y = fmaf(h0, w.y, a0.y);
        a0.z = fmaf(h0, w.z, a0.z); a0.w = fmaf(h0, w.w, a0.w);
        a1.x = fmaf(h1, w.x, a1.x); a1.y = fmaf(h1, w.y, a1.y);
        a1.z = fmaf(h1, w.z, a1.z); a1.w = fmaf(h1, w.w, a1.w);
        a2.x = fmaf(h2, w.x, a2.x); a2.y = fmaf(h2, w.y, a2.y);
        a2.z = fmaf(h2, w.z, a2.z); a2.w = fmaf(h2, w.w, a2.w);
        a3.x = fmaf(h3, w.x, a3.x); a3.y = fmaf(h3, w.y, a3.y);
        a3.z = fmaf(h3, w.z, a3.z); a3.w = fmaf(h3, w.w, a3.w);
    }
    sred[dg][0][cg] = a0;
    sred[dg][1][cg] = a1;
    sred[dg][2][cg] = a2;
    sred[dg][3][cg] = a3;
    __syncthreads();
    {
        const int b = tid >> 6, l = tid & 63;
        float4 s0 = sred[0][b][l], s1 = sred[1][b][l];
        float4 s2 = sred[2][b][l], s3 = sred[3][b][l];
        float* dst = &g_hfinal[b][blockIdx.x * 256 + l * 4];
        atomicAdd(dst + 0, (s0.x + s1.x) + (s2.x + s3.x));
        atomicAdd(dst + 1, (s0.y + s1.y) + (s2.y + s3.y));
        atomicAdd(dst + 2, (s0.z + s1.z) + (s2.z + s3.z));
        atomicAdd(dst + 3, (s0.w + s1.w) + (s2.w + s3.w));
    }
}

// ---------------- K6: out += (hfinal + hlast) @ out_w (atomic into d_out) --
__global__ void k6_out(const float* __restrict__ out_w,
                       float* __restrict__ out) {
    __shared__ float  shf[NB][O_DCH];
    __shared__ float4 sred[4][NB][64];
    const int dc = blockIdx.y;
    const int tid = threadIdx.x;
    const int lane4 = tid & 63;       // col group: 4 cols
    const int dgrp  = tid >> 6;       // 0..3, 32 d-rows each
    for (int t = tid; t < NB * O_DCH; t += 256) {
        int b = t >> 7, d = t & (O_DCH - 1);
        shf[b][d] = g_hfinal[b][dc * O_DCH + d] + g_hlast[b][dc * O_DCH + d];
    }
    __syncthreads();
    const int v = blockIdx.x * 256 + lane4 * 4;
    const int d0 = dgrp * 32;
    float4 a0 = {0,0,0,0}, a1 = {0,0,0,0}, a2 = {0,0,0,0}, a3 = {0,0,0,0};
#pragma unroll 8
    for (int i = 0; i < 32; i++) {
        const int d = d0 + i;
        float4 w = *(const float4*)(out_w + (size_t)(dc * O_DCH + d) * NV + v);
        float h0 = shf[0][d], h1 = shf[1][d], h2 = shf[2][d], h3 = shf[3][d];
        a0.x = fmaf(h0, w.x, a0.x); a0.y = fmaf(h0, w.y, a0.y);
        a0.z = fmaf(h0, w.z, a0.z); a0.w = fmaf(h0, w.w, a0.w);
        a1.x = fmaf(h1, w.x, a1.x); a1.y = fmaf(h1, w.y, a1.y);
        a1.z = fmaf(h1, w.z, a1.z); a1.w = fmaf(h1, w.w, a1.w);
        a2.x = fmaf(h2, w.x, a2.x); a2.y = fmaf(h2, w.y, a2.y);
        a2.z = fmaf(h2, w.z, a2.z); a2.w = fmaf(h2, w.w, a2.w);
        a3.x = fmaf(h3, w.x, a3.x); a3.y = fmaf(h3, w.y, a3.y);
        a3.z = fmaf(h3, w.z, a3.z); a3.w = fmaf(h3, w.w, a3.w);
    }
    sred[dgrp][0][lane4] = a0;
    sred[dgrp][1][lane4] = a1;
    sred[dgrp][2][lane4] = a2;
    sred[dgrp][3][lane4] = a3;
    __syncthreads();
    {
        const int b = tid >> 6, l = tid & 63;   // 256 threads = 4 b x 64 lanes
        float4 s0 = sred[0][b][l], s1 = sred[1][b][l];
        float4 s2 = sred[2][b][l], s3 = sred[3][b][l];
        float* dst = out + b * NV + blockIdx.x * 256 + l * 4;
        atomicAdd(dst + 0, (s0.x + s1.x) + (s2.x + s3.x));
        atomicAdd(dst + 1, (s0.y + s1.y) + (s2.y + s3.y));
        atomicAdd(dst + 2, (s0.z + s1.z) + (s2.z + s3.z));
        atomicAdd(dst + 3, (s0.w + s1.w) + (s2.w + s3.w));
    }
}

extern "C" void kernel_launch(void* const* d_in, const int* in_sizes, int n_in,
                              void* d_out, int out_size) {
    const void*  x      = d_in[0];
    const float* embed  = (const float*)d_in[1];
    const float* qkv_w  = (const float*)d_in[2];
    const float* qkv_b  = (const float*)d_in[3];
    const float* out_w  = (const float*)d_in[4];
    const float* out_b  = (const float*)d_in[5];
    float* out = (float*)d_out;

    kinit<<<NV / 256, 256>>>(qkv_b, out_b, out);
    k1a_qpart<<<dim3(4, QK_DSPLIT), 256>>>(x, embed, qkv_w);
    k1b_qk<<<513, 256>>>(qkv_w, qkv_b);
    k2_logits<<<dim3(NS / 16, NB), 256>>>(x, embed);
    k3_softmax<<<NB, 1024>>>();
    k4_hbar<<<dim3(HB_CHUNK, NB), 256>>>(x, embed);
    k5a_vpart<<<dim3(4, V_DSPLIT), 256>>>(qkv_w);
    k6_out<<<dim3(NV / 256, O_DSPLIT), 256>>>(out_w, out);
}

// round 16
// speedup vs baseline: 1.0684x; 1.0358x over previous
#include <cuda_runtime.h>
#include <cstdint>
#include <math_constants.h>

#define NB 4
#define NS 4096
#define ND 1024
#define NV 32000
#define ND3 3072

#define QK_DSPLIT 64
#define QK_DCH (ND / QK_DSPLIT)      // 16
#define CH 128                       // softmax/hbar chunks per batch
#define V_DSPLIT 64
#define V_DCH (ND / V_DSPLIT)        // 16
#define O_DSPLIT 8
#define O_DCH (ND / O_DSPLIT)        // 128

// ---------------- scratch (device globals; no allocation allowed) ----------
__device__ __align__(16) float g_hlast[NB][ND];
__device__ __align__(16) float g_qlast[NB][ND];       // accum: init bias_q
__device__ __align__(16) float g_qk[NB][ND];          // pre-scaled by 1/32
__device__ __align__(16) float g_hp[NB][CH][ND];      // partial hbar (unnorm)
__device__ float g_hm[NB][CH];                        // partial max
__device__ float g_hz[NB][CH];                        // partial Z
__device__ __align__(16) float g_hbar[NB][ND];        // merged hbar
__device__ __align__(16) float g_hfinal[NB][ND];      // accum: init bias_v

__device__ __forceinline__ int get_idx(const void* x, int i, bool is64) {
    if (is64) return (int)((const long long*)x)[i];
    return ((const int*)x)[i];
}

// ---------------- KINIT: initialize accumulators ---------------------------
__global__ void kinit(const float* __restrict__ qkv_b,
                      const float* __restrict__ out_b,
                      float* __restrict__ out) {
    const int v = blockIdx.x * 256 + threadIdx.x;   // 0..31999
    const float ob = out_b[v];
    out[0 * NV + v] = ob;
    out[1 * NV + v] = ob;
    out[2 * NV + v] = ob;
    out[3 * NV + v] = ob;
    if (blockIdx.x < 16) {
        int idx = blockIdx.x * 256 + threadIdx.x;   // 0..4095
        int b = idx >> 10, j = idx & (ND - 1);
        g_qlast[b][j]  = qkv_b[j];
        g_hfinal[b][j] = qkv_b[2048 + j];
    }
}

// ---------------- K1a: q_last partials -> atomicAdd into g_qlast -----------
__global__ void k1a_qpart(const void* __restrict__ x,
                          const float* __restrict__ embed,
                          const float* __restrict__ qkv_w) {
    __shared__ float  sh[NB][QK_DCH];
    __shared__ float4 sred[4][NB][64];
    const int tid = threadIdx.x;
    int vdet = (tid < 64) ? ((const int*)x)[2 * tid + 1] : 0;
    const bool is64 = (__syncthreads_or(vdet) == 0);
    const int dch = blockIdx.y;
    if (tid < NB * QK_DCH) {
        int b = tid / QK_DCH, d = tid % QK_DCH;
        int row = get_idx(x, b * NS + NS - 1, is64);
        float v = embed[(size_t)row * ND + dch * QK_DCH + d];
        sh[b][d] = v;
        if (blockIdx.x == 0) g_hlast[b][dch * QK_DCH + d] = v;
    }
    __syncthreads();
    const int cg = tid & 63, dg = tid >> 6;
    const int j = blockIdx.x * 256 + cg * 4;
    float4 a0 = {0,0,0,0}, a1 = {0,0,0,0}, a2 = {0,0,0,0}, a3 = {0,0,0,0};
#pragma unroll
    for (int i = 0; i < 4; i++) {
        const int d = dg * 4 + i;
        float4 w = *(const float4*)(qkv_w + (size_t)(dch * QK_DCH + d) * ND3 + j);
        float h0 = sh[0][d], h1 = sh[1][d], h2 = sh[2][d], h3 = sh[3][d];
        a0.x = fmaf(h0, w.x, a0.x); a0.y = fmaf(h0, w.y, a0.y);
        a0.z = fmaf(h0, w.z, a0.z); a0.w = fmaf(h0, w.w, a0.w);
        a1.x = fmaf(h1, w.x, a1.x); a1.y = fmaf(h1, w.y, a1.y);
        a1.z = fmaf(h1, w.z, a1.z); a1.w = fmaf(h1, w.w, a1.w);
        a2.x = fmaf(h2, w.x, a2.x); a2.y = fmaf(h2, w.y, a2.y);
        a2.z = fmaf(h2, w.z, a2.z); a2.w = fmaf(h2, w.w, a2.w);
        a3.x = fmaf(h3, w.x, a3.x); a3.y = fmaf(h3, w.y, a3.y);
        a3.z = fmaf(h3, w.z, a3.z); a3.w = fmaf(h3, w.w, a3.w);
    }
    sred[dg][0][cg] = a0;
    sred[dg][1][cg] = a1;
    sred[dg][2][cg] = a2;
    sred[dg][3][cg] = a3;
    __syncthreads();
    {
        const int b = tid >> 6, l = tid & 63;
        float4 s0 = sred[0][b][l], s1 = sred[1][b][l];
        float4 s2 = sred[2][b][l], s3 = sred[3][b][l];
        float* dst = &g_qlast[b][blockIdx.x * 256 + l * 4];
        atomicAdd(dst + 0, (s0.x + s1.x) + (s2.x + s3.x));
        atomicAdd(dst + 1, (s0.y + s1.y) + (s2.y + s3.y));
        atomicAdd(dst + 2, (s0.z + s1.z) + (s2.z + s3.z));
        atomicAdd(dst + 3, (s0.w + s1.w) + (s2.w + s3.w));
    }
}

// ---------------- K1b: qk[j] = Wk-row(j) . q_last (no bias; shift cancels) -
__global__ void k1b_qk(const float* __restrict__ qkv_w) {
    __shared__ float4 sq[NB][256];    // qlast, 16 KB
    __shared__ float red[2][4][NB];
    const int tid = threadIdx.x, warp = tid >> 5, lane = tid & 31;
    const float kInv = 0.03125f;                  // 1/sqrt(1024)
    const int rloc = warp >> 2;               // 0..1
    const int quad = warp & 3;                // 0..3
    const int j = blockIdx.x * 2 + rloc;
    const float4* wrow = (const float4*)(qkv_w + (size_t)j * ND3 + ND);
    const int p0 = quad * 64 + lane;
    const int p1 = quad * 64 + 32 + lane;
    float4 w0 = wrow[p0];
    float4 w1 = wrow[p1];
    {
        float4 t0 = ((const float4*)g_qlast[0])[tid];
        float4 t1 = ((const float4*)g_qlast[1])[tid];
        float4 t2 = ((const float4*)g_qlast[2])[tid];
        float4 t3 = ((const float4*)g_qlast[3])[tid];
        sq[0][tid] = t0; sq[1][tid] = t1; sq[2][tid] = t2; sq[3][tid] = t3;
    }
    __syncthreads();
    float a0, a1, a2, a3;
    {
        float4 q0 = sq[0][p0], q1 = sq[1][p0], q2 = sq[2][p0], q3 = sq[3][p0];
        a0 = fmaf(w0.x, q0.x, fmaf(w0.y, q0.y, fmaf(w0.z, q0.z, w0.w * q0.w)));
        a1 = fmaf(w0.x, q1.x, fmaf(w0.y, q1.y, fmaf(w0.z, q1.z, w0.w * q1.w)));
        a2 = fmaf(w0.x, q2.x, fmaf(w0.y, q2.y, fmaf(w0.z, q2.z, w0.w * q2.w)));
        a3 = fmaf(w0.x, q3.x, fmaf(w0.y, q3.y, fmaf(w0.z, q3.z, w0.w * q3.w)));
    }
    {
        float4 q0 = sq[0][p1], q1 = sq[1][p1], q2 = sq[2][p1], q3 = sq[3][p1];
        a0 = fmaf(w1.x, q0.x, fmaf(w1.y, q0.y, fmaf(w1.z, q0.z, fmaf(w1.w, q0.w, a0))));
        a1 = fmaf(w1.x, q1.x, fmaf(w1.y, q1.y, fmaf(w1.z, q1.z, fmaf(w1.w, q1.w, a1))));
        a2 = fmaf(w1.x, q2.x, fmaf(w1.y, q2.y, fmaf(w1.z, q2.z, fmaf(w1.w, q2.w, a2))));
        a3 = fmaf(w1.x, q3.x, fmaf(w1.y, q3.y, fmaf(w1.z, q3.z, fmaf(w1.w, q3.w, a3))));
    }
#pragma unroll
    for (int o = 16; o > 0; o >>= 1) {
        a0 += __shfl_xor_sync(0xffffffffu, a0, o);
        a1 += __shfl_xor_sync(0xffffffffu, a1, o);
        a2 += __shfl_xor_sync(0xffffffffu, a2, o);
        a3 += __shfl_xor_sync(0xffffffffu, a3, o);
    }
    if (lane == 0) {
        red[rloc][quad][0] = a0; red[rloc][quad][1] = a1;
        red[rloc][quad][2] = a2; red[rloc][quad][3] = a3;
    }
    __syncthreads();
    if (tid < 8) {
        int r = tid >> 2, b = tid & 3;
        float s = red[r][0][b] + red[r][1][b] + red[r][2][b] + red[r][3][b];
        g_qk[b][blockIdx.x * 2 + r] = s * kInv;
    }
}

// ---------------- K2F: fused gather: logits + online softmax + hbar --------
// Grid (CH, NB) = (128, 4). 8 warps x 4 rows each. Single pass over embed:
// row registers serve both the dot (logit) and the weighted accumulation.
__global__ void __launch_bounds__(256, 2)
k2f_fused(const void* __restrict__ x,
          const float* __restrict__ embed) {
    __shared__ float4 sqk[256];
    __shared__ float4 accbuf[8][256];   // 32 KB
    __shared__ float wm[8], wz2[8];
    const int b = blockIdx.y;
    const int tid = threadIdx.x;
    int vdet = (tid < 64) ? ((const int*)x)[2 * tid + 1] : 0;
    sqk[tid] = ((const float4*)g_qk[b])[tid];
    const bool is64 = (__syncthreads_or(vdet) == 0);   // also the sqk barrier
    const int warp = tid >> 5, lane = tid & 31;
    const int s0 = blockIdx.x * 32 + warp * 4;
    float m = -CUDART_INF_F, Z = 0.f;
    float4 acc[8];
#pragma unroll
    for (int it = 0; it < 8; it++) acc[it] = make_float4(0.f, 0.f, 0.f, 0.f);
    for (int r = 0; r < 4; r++) {
        const int row = get_idx(x, b * NS + s0 + r, is64);
        const float4* e = (const float4*)(embed + (size_t)row * ND);
        float4 ra[8];
#pragma unroll
        for (int it = 0; it < 8; it++) ra[it] = e[lane + 32 * it];
        float d = 0.f;
#pragma unroll
        for (int it = 0; it < 8; it++) {
            float4 q = sqk[lane + 32 * it];
            d = fmaf(ra[it].x, q.x, fmaf(ra[it].y, q.y, fmaf(ra[it].z, q.z, fmaf(ra[it].w, q.w, d))));
        }
#pragma unroll
        for (int o = 16; o > 0; o >>= 1) d += __shfl_xor_sync(0xffffffffu, d, o);
        float newm = fmaxf(m, d);
        float so = expf(m - newm);   // 0 on first iteration (m = -inf)
        float ws = expf(d - newm);
        Z = fmaf(Z, so, ws);
#pragma unroll
        for (int it = 0; it < 8; it++) {
            acc[it].x = fmaf(acc[it].x, so, ws * ra[it].x);
            acc[it].y = fmaf(acc[it].y, so, ws * ra[it].y);
            acc[it].z = fmaf(acc[it].z, so, ws * ra[it].z);
            acc[it].w = fmaf(acc[it].w, so, ws * ra[it].w);
        }
        m = newm;
    }
    if (lane == 0) wm[warp] = m;
    __syncthreads();
    float M = wm[0];
#pragma unroll
    for (int w = 1; w < 8; w++) M = fmaxf(M, wm[w]);
    const float f = expf(m - M);
    if (lane == 0) wz2[warp] = Z * f;
#pragma unroll
    for (int it = 0; it < 8; it++) {
        float4 a = acc[it];
        a.x *= f; a.y *= f; a.z *= f; a.w *= f;
        accbuf[warp][lane + 32 * it] = a;
    }
    __syncthreads();
    {
        float4 s = accbuf[0][tid];
#pragma unroll
        for (int w = 1; w < 8; w++) {
            float4 t = accbuf[w][tid];
            s.x += t.x; s.y += t.y; s.z += t.z; s.w += t.w;
        }
        ((float4*)g_hp[b][blockIdx.x])[tid] = s;
    }
    if (tid == 0) {
        g_hm[b][blockIdx.x] = M;
        g_hz[b][blockIdx.x] = ((wz2[0] + wz2[1]) + (wz2[2] + wz2[3]))
                            + ((wz2[4] + wz2[5]) + (wz2[6] + wz2[7]));
    }
}

// ---------------- KCOMB: merge CH partials -> normalized g_hbar ------------
// Grid (8, NB), 128 threads; thread owns one j column.
__global__ void kcomb() {
    __shared__ float sm_[CH], sf[CH], sz[CH];
    const int b = blockIdx.y;
    const int tid = threadIdx.x;
    sm_[tid] = g_hm[b][tid];
    sz[tid]  = g_hz[b][tid];
    __syncthreads();
    float M = sm_[0];
#pragma unroll 16
    for (int c = 1; c < CH; c++) M = fmaxf(M, sm_[c]);
    sf[tid] = expf(sm_[tid] - M);
    __syncthreads();
    float Zt = 0.f;
#pragma unroll 16
    for (int c = 0; c < CH; c++) Zt = fmaf(sf[c], sz[c], Zt);
    const int j = blockIdx.x * 128 + tid;
    float s = 0.f;
#pragma unroll 8
    for (int c = 0; c < CH; c++) s = fmaf(sf[c], g_hp[b][c][j], s);
    g_hbar[b][j] = s / Zt;
}

// ---------------- K5a: v partials = hbar @ Wv -> atomicAdd g_hfinal --------
__global__ void k5a_vpart(const float* __restrict__ qkv_w) {
    __shared__ float  sh[NB][V_DCH];
    __shared__ float4 sred[4][NB][64];
    const int dch = blockIdx.y;
    const int tid = threadIdx.x;
    if (tid < NB * V_DCH) {
        int b = tid >> 4, d = tid & 15;
        sh[b][d] = g_hbar[b][dch * V_DCH + d];
    }
    __syncthreads();
    const int cg = tid & 63, dg = tid >> 6;
    const int j = blockIdx.x * 256 + cg * 4;
    float4 a0 = {0,0,0,0}, a1 = {0,0,0,0}, a2 = {0,0,0,0}, a3 = {0,0,0,0};
#pragma unroll
    for (int i = 0; i < 4; i++) {
        const int d = dg * 4 + i;
        float4 w = *(const float4*)(qkv_w + (size_t)(dch * V_DCH + d) * ND3 + 2048 + j);
        float h0 = sh[0][d], h1 = sh[1][d], h2 = sh[2][d], h3 = sh[3][d];
        a0.x = fmaf(h0, w.x, a0.x); a0.y = fmaf(h0, w.y, a0.y);
        a0.z = fmaf(h0, w.z, a0.z); a0.w = fmaf(h0, w.w, a0.w);
        a1.x = fmaf(h1, w.x, a1.x); a1.y = fmaf(h1, w.y, a1.y);
        a1.z = fmaf(h1, w.z, a1.z); a1.w = fmaf(h1, w.w, a1.w);
        a2.x = fmaf(h2, w.x, a2.x); a2.y = fmaf(h2, w.y, a2.y);
        a2.z = fmaf(h2, w.z, a2.z); a2.w = fmaf(h2, w.w, a2.w);
        a3.x = fmaf(h3, w.x, a3.x); a3.y = fmaf(h3, w.y, a3.y);
        a3.z = fmaf(h3, w.z, a3.z); a3.w = fmaf(h3, w.w, a3.w);
    }
    sred[dg][0][cg] = a0;
    sred[dg][1][cg] = a1;
    sred[dg][2][cg] = a2;
    sred[dg][3][cg] = a3;
    __syncthreads();
    {
        const int b = tid >> 6, l = tid & 63;
        float4 s0 = sred[0][b][l], s1 = sred[1][b][l];
        float4 s2 = sred[2][b][l], s3 = sred[3][b][l];
        float* dst = &g_hfinal[b][blockIdx.x * 256 + l * 4];
        atomicAdd(dst + 0, (s0.x + s1.x) + (s2.x + s3.x));
        atomicAdd(dst + 1, (s0.y + s1.y) + (s2.y + s3.y));
        atomicAdd(dst + 2, (s0.z + s1.z) + (s2.z + s3.z));
        atomicAdd(dst + 3, (s0.w + s1.w) + (s2.w + s3.w));
    }
}

// ---------------- K6: out += (hfinal + hlast) @ out_w (atomic into d_out) --
__global__ void k6_out(const float* __restrict__ out_w,
                       float* __restrict__ out) {
    __shared__ float  shf[NB][O_DCH];
    __shared__ float4 sred[4][NB][64];
    const int dc = blockIdx.y;
    const int tid = threadIdx.x;
    const int lane4 = tid & 63;       // col group: 4 cols
    const int dgrp  = tid >> 6;       // 0..3, 32 d-rows each
    for (int t = tid; t < NB * O_DCH; t += 256) {
        int b = t >> 7, d = t & (O_DCH - 1);
        shf[b][d] = g_hfinal[b][dc * O_DCH + d] + g_hlast[b][dc * O_DCH + d];
    }
    __syncthreads();
    const int v = blockIdx.x * 256 + lane4 * 4;
    const int d0 = dgrp * 32;
    float4 a0 = {0,0,0,0}, a1 = {0,0,0,0}, a2 = {0,0,0,0}, a3 = {0,0,0,0};
#pragma unroll 8
    for (int i = 0; i < 32; i++) {
        const int d = d0 + i;
        float4 w = *(const float4*)(out_w + (size_t)(dc * O_DCH + d) * NV + v);
        float h0 = shf[0][d], h1 = shf[1][d], h2 = shf[2][d], h3 = shf[3][d];
        a0.x = fmaf(h0, w.x, a0.x); a0.y = fmaf(h0, w.y, a0.y);
        a0.z = fmaf(h0, w.z, a0.z); a0.w = fmaf(h0, w.w, a0.w);
        a1.x = fmaf(h1, w.x, a1.x); a1.y = fmaf(h1, w.y, a1.y);
        a1.z = fmaf(h1, w.z, a1.z); a1.w = fmaf(h1, w.w, a1.w);
        a2.x = fmaf(h2, w.x, a2.x); a2.y = fmaf(h2, w.y, a2.y);
        a2.z = fmaf(h2, w.z, a2.z); a2.w = fmaf(h2, w.w, a2.w);
        a3.x = fmaf(h3, w.x, a3.x); a3.y = fmaf(h3, w.y, a3.y);
        a3.z = fmaf(h3, w.z, a3.z); a3.w = fmaf(h3, w.w, a3.w);
    }
    sred[dgrp][0][lane4] = a0;
    sred[dgrp][1][lane4] = a1;
    sred[dgrp][2][lane4] = a2;
    sred[dgrp][3][lane4] = a3;
    __syncthreads();
    {
        const int b = tid >> 6, l = tid & 63;   // 256 threads = 4 b x 64 lanes
        float4 s0 = sred[0][b][l], s1 = sred[1][b][l];
        float4 s2 = sred[2][b][l], s3 = sred[3][b][l];
        float* dst = out + b * NV + blockIdx.x * 256 + l * 4;
        atomicAdd(dst + 0, (s0.x + s1.x) + (s2.x + s3.x));
        atomicAdd(dst + 1, (s0.y + s1.y) + (s2.y + s3.y));
        atomicAdd(dst + 2, (s0.z + s1.z) + (s2.z + s3.z));
        atomicAdd(dst + 3, (s0.w + s1.w) + (s2.w + s3.w));
    }
}

extern "C" void kernel_launch(void* const* d_in, const int* in_sizes, int n_in,
                              void* d_out, int out_size) {
    const void*  x      = d_in[0];
    const float* embed  = (const float*)d_in[1];
    const float* qkv_w  = (const float*)d_in[2];
    const float* qkv_b  = (const float*)d_in[3];
    const float* out_w  = (const float*)d_in[4];
    const float* out_b  = (const float*)d_in[5];
    float* out = (float*)d_out;

    kinit<<<NV / 256, 256>>>(qkv_b, out_b, out);
    k1a_qpart<<<dim3(4, QK_DSPLIT), 256>>>(x, embed, qkv_w);
    k1b_qk<<<512, 256>>>(qkv_w);
    k2f_fused<<<dim3(CH, NB), 256>>>(x, embed);
    kcomb<<<dim3(8, NB), 128>>>();
    k5a_vpart<<<dim3(4, V_DSPLIT), 256>>>(qkv_w);
    k6_out<<<dim3(NV / 256, O_DSPLIT), 256>>>(out_w, out);
}